// round 16
// baseline (speedup 1.0000x reference)
#include <cuda_runtime.h>
#include <cuda_bf16.h>
#include <cstdint>

#define NN 50000
#define EE 800000
#define HH 128
#define TH 384
#define NTILES (EE / 64)

// scratch: x_h [N][384] fp32; We pre-split bf16 hi/lo packed per (colgroup, kchunk, half)
__device__ __align__(16) float g_xh[(size_t)NN * TH];
__device__ __align__(16) unsigned char g_WeB[4 * 8 * 2 * 3072];   // 196608 B

// ---------------- PTX helpers ----------------
#define PACK2(d, lo, hi) \
    asm volatile("mov.b64 %0, {%1, %2};" : "=l"(d) : "f"(lo), "f"(hi))
#define UNPACK2(lo, hi, s) \
    asm volatile("mov.b64 {%0, %1}, %2;" : "=f"(lo), "=f"(hi) : "l"(s))
#define FMA2(c_, a_, b_) \
    asm volatile("fma.rn.f32x2 %0, %1, %2, %0;" : "+l"(c_) : "l"(a_), "l"(b_))
#define RED2(p_, a_, b_) \
    asm volatile("red.global.add.v2.f32 [%0], {%1, %2};" \
                 :: "l"(p_), "f"(a_), "f"(b_) : "memory")
#define CP_ASYNC16(dst_s, src_g) \
    asm volatile("cp.async.cg.shared.global [%0], [%1], 16;" :: "r"(dst_s), "l"(src_g))
#define CP_COMMIT() asm volatile("cp.async.commit_group;")
#define CP_WAIT0()  asm volatile("cp.async.wait_group 0;")
#define CP_WAIT1()  asm volatile("cp.async.wait_group 1;")
#define CVT_BF16X2(d_, hi_, lo_) \
    asm volatile("cvt.rn.bf16x2.f32 %0, %1, %2;" : "=r"(d_) : "f"(hi_), "f"(lo_))

#define LDSM4(f_, addr_) \
    asm volatile("ldmatrix.sync.aligned.m8n8.x4.shared.b16 {%0,%1,%2,%3}, [%4];" \
        : "=r"((f_)[0]), "=r"((f_)[1]), "=r"((f_)[2]), "=r"((f_)[3]) : "r"(addr_))
#define MMA(c_, a_, b0_, b1_) \
    asm volatile("mma.sync.aligned.m16n8k16.row.col.f32.bf16.bf16.f32 " \
        "{%0,%1,%2,%3}, {%4,%5,%6,%7}, {%8,%9}, {%0,%1,%2,%3};" \
        : "+f"((c_)[0]), "+f"((c_)[1]), "+f"((c_)[2]), "+f"((c_)[3]) \
        : "r"((a_)[0]), "r"((a_)[1]), "r"((a_)[2]), "r"((a_)[3]), "r"(b0_), "r"(b1_))

// ---------------- zero output ----------------
__global__ void zero_kernel(float4* __restrict__ p, long long n4) {
    long long i = (long long)blockIdx.x * blockDim.x + threadIdx.x;
    if (i < n4) p[i] = make_float4(0.f, 0.f, 0.f, 0.f);
}

// ---------------- prep: We [K=128][N=384] fp32 -> bf16 hi/lo packed ----------------
__global__ void prep_we(const float* __restrict__ We) {
    int idx = blockIdx.x * 256 + threadIdx.x;    // n*128 + k
    if (idx >= 384 * 128) return;
    int n = idx >> 7, k = idx & 127;
    float v = We[(size_t)k * 384 + n];
    __nv_bfloat16 h = __float2bfloat16(v);
    __nv_bfloat16 l = __float2bfloat16(v - __bfloat162float(h));
    int chunk = n >> 7, rem = n & 127;
    int g = rem >> 5, w32 = rem & 31;
    int s = w32 >> 4, u = w32 & 15;
    int rr = s * 48 + chunk * 16 + u;
    int kc = k >> 4, kin = k & 15;
    uint32_t off = (uint32_t)(((g * 8 + kc) * 2) * 3072 + rr * 32
                              + ((kin >> 3) & 1) * 16 + (kin & 7) * 2);
    *(unsigned short*)(g_WeB + off)        = __bfloat16_as_ushort(h);
    *(unsigned short*)(g_WeB + off + 3072) = __bfloat16_as_ushort(l);
}

// ---------------- node kernel v2 (unchanged from R12) ----------------
__global__ __launch_bounds__(128) void node_kernel(
    const float* __restrict__ x, const float* __restrict__ W1,
    const float* __restrict__ b1, const float* __restrict__ W2,
    const float* __restrict__ b2)
{
    __shared__ __align__(16) float xs[128 * 16];
    __shared__ __align__(16) float w1s[128 * 64];
    __shared__ __align__(16) float hs[64 * 20];

    const int t = threadIdx.x;
    const int node0 = blockIdx.x * 16;

    {
        const float4* W14 = (const float4*)W1;
        float4* w1s4 = (float4*)w1s;
#pragma unroll
        for (int r = 0; r < 16; r++) w1s4[t + r * 128] = W14[t + r * 128];
    }
    const float4* x4 = (const float4*)x;
#pragma unroll
    for (int r = 0; r < 4; r++) {
        int idx = t + r * 128;
        int n = idx & 15, kq = idx >> 4;
        float4 v = x4[(size_t)(node0 + n) * 32 + kq];
        xs[(kq * 4 + 0) * 16 + n] = v.x;
        xs[(kq * 4 + 1) * 16 + n] = v.y;
        xs[(kq * 4 + 2) * 16 + n] = v.z;
        xs[(kq * 4 + 3) * 16 + n] = v.w;
    }
    __syncthreads();

    {
        const int c = t & 63, nh = t >> 6;
        unsigned long long a2[4];
        float b1c = b1[c];
        unsigned long long binit; PACK2(binit, b1c, b1c);
#pragma unroll
        for (int p = 0; p < 4; p++) a2[p] = binit;
        const unsigned long long* xp = (const unsigned long long*)xs;
#pragma unroll 4
        for (int k = 0; k < 128; k++) {
            float w = w1s[k * 64 + c];
            unsigned long long wp; PACK2(wp, w, w);
            const unsigned long long* xr = xp + k * 8 + nh * 4;
            FMA2(a2[0], xr[0], wp);
            FMA2(a2[1], xr[1], wp);
            FMA2(a2[2], xr[2], wp);
            FMA2(a2[3], xr[3], wp);
        }
#pragma unroll
        for (int p = 0; p < 4; p++) {
            float lo, hi; UNPACK2(lo, hi, a2[p]);
            lo = lo / (1.f + __expf(-lo)) * 1.6666666666666667f;
            hi = hi / (1.f + __expf(-hi)) * 1.6666666666666667f;
            unsigned long long pk; PACK2(pk, lo, hi);
            *(unsigned long long*)&hs[c * 20 + (nh * 4 + p) * 2] = pk;
        }
    }
    __syncthreads();

    {
        unsigned long long acc2[24];
#pragma unroll
        for (int a = 0; a < 24; a++) acc2[a] = 0ull;
#pragma unroll 2
        for (int k = 0; k < 64; k++) {
            const float* wr = W2 + k * 384 + t;
            float w0 = wr[0], w1 = wr[128], w2 = wr[256];
            unsigned long long wp0, wp1, wp2;
            PACK2(wp0, w0, w0); PACK2(wp1, w1, w1); PACK2(wp2, w2, w2);
            const unsigned long long* hp = (const unsigned long long*)&hs[k * 20];
#pragma unroll
            for (int p = 0; p < 8; p++) {
                unsigned long long hv = hp[p];
                FMA2(acc2[p],      hv, wp0);
                FMA2(acc2[8 + p],  hv, wp1);
                FMA2(acc2[16 + p], hv, wp2);
            }
        }
        const float bc0 = b2[t], bc1 = b2[t + 128], bc2 = b2[t + 256];
#pragma unroll
        for (int p = 0; p < 8; p++) {
            float* o0 = g_xh + (size_t)(node0 + 2 * p) * 384 + t;
            float* o1 = o0 + 384;
            float lo, hi;
            UNPACK2(lo, hi, acc2[p]);      o0[0]   = lo + bc0; o1[0]   = hi + bc0;
            UNPACK2(lo, hi, acc2[8 + p]);  o0[128] = lo + bc1; o1[128] = hi + bc1;
            UNPACK2(lo, hi, acc2[16 + p]); o0[256] = lo + bc2; o1[256] = hi + bc2;
        }
    }
}

// ---------------- edge kernel (R12 + hoisted addressing + B0-first ordering) ---------
// 256 threads, M=64 edges x N=96 GEMM cols (col-group g: output cols {g*32..}+0/128/256).
// grid = 12500 edge-tiles * 4 col groups, col group fastest (L2 reuse of rbf tile).
// smem:
//   [0:256) js  [256:512) is  [512:1280) evs[192]  [1280:2816) bes[384]
//   [4096:20480)  A hi 64x128 bf16 swizzled   [20480:36864) A lo
//   [36864:64512) B triple buffer: buf b at +b*9216 { hi 96x48B, lo +4608 }
#define A_OFF 4096
#define B_OFF 36864
#define EDGE_SMEM 64512

__global__ __launch_bounds__(256, 3) void edge_kernel(
    const float* __restrict__ edge_rbf, const float* __restrict__ edge_vector,
    const int* __restrict__ edge_index, const float* __restrict__ be,
    const float* __restrict__ vec, float* __restrict__ d_x, float* __restrict__ d_vec)
{
    extern __shared__ __align__(16) unsigned char sm[];
    const uint32_t smb = (uint32_t)__cvta_generic_to_shared(sm);
    const int tid = threadIdx.x;
    const int wid = tid >> 5;
    const int lane = tid & 31;
    const int g = blockIdx.x & 3;
    const int e0 = (blockIdx.x >> 2) * 64;

    int* js   = (int*)(sm);
    int* is_  = (int*)(sm + 256);
    float* evs = (float*)(sm + 512);
    float* bes = (float*)(sm + 1280);

    // ---- hoisted cp.async per-thread addressing (loop-invariant) ----
    // thread covers id0 = tid (<384 always since 256<384) and id1 = tid+256 (if <384)
    const int id0 = tid;
    const int h0 = id0 / 192, r0_ = id0 - h0 * 192;
    const uint32_t dsto0 = (uint32_t)(h0 * 4608 + (r0_ >> 1) * 48 + (r0_ & 1) * 16);
    const uint32_t srco0 = (uint32_t)(h0 * 3072 + (r0_ >> 1) * 32 + (r0_ & 1) * 16);
    const bool two = (tid < 128);
    const int id1 = tid + 256;
    const int h1 = id1 / 192, r1_ = id1 - h1 * 192;
    const uint32_t dsto1 = (uint32_t)(h1 * 4608 + (r1_ >> 1) * 48 + (r1_ & 1) * 16);
    const uint32_t srco1 = (uint32_t)(h1 * 3072 + (r1_ >> 1) * 32 + (r1_ & 1) * 16);

    // ---- B chunk 0 prefetch FIRST (overlaps with A build below) ----
    {
        const unsigned char* bsrc0 = g_WeB + (size_t)(g * 8) * 6144;
        CP_ASYNC16(smb + B_OFF + dsto0, bsrc0 + srco0);
        if (two) CP_ASYNC16(smb + B_OFF + dsto1, bsrc0 + srco1);
        CP_COMMIT();
    }

    if (tid < 64) {
        js[tid]  = edge_index[e0 + tid];
        is_[tid] = edge_index[EE + e0 + tid];
    }
    if (tid < 192) evs[tid] = edge_vector[(size_t)e0 * 3 + tid];
    for (int id = tid; id < 384; id += 256) bes[id] = be[id];

    // ---- A: load fp32 rbf, truncation-split to bf16 hi/lo, swizzled store ----
    // strength-reduced: e = wid + r*8 (e&7 == wid), q = lane.
    {
        const uint32_t abase = (uint32_t)(wid * 256 + (((lane >> 1) ^ wid) << 4)
                                          + (lane & 1) * 8);
        const float4* rsrc = (const float4*)edge_rbf + (size_t)(e0 + wid) * 32 + lane;
#pragma unroll
        for (int r = 0; r < 8; r++) {
            float4 v = rsrc[r * 256];              // (+8 edges) * 32 float4
            uint32_t bx = __float_as_uint(v.x), by = __float_as_uint(v.y);
            uint32_t bz = __float_as_uint(v.z), bw = __float_as_uint(v.w);
            uint32_t ph01 = __byte_perm(bx, by, 0x7632);
            uint32_t ph23 = __byte_perm(bz, bw, 0x7632);
            float hx = __uint_as_float(bx & 0xFFFF0000u);
            float hy = __uint_as_float(by & 0xFFFF0000u);
            float hz = __uint_as_float(bz & 0xFFFF0000u);
            float hw = __uint_as_float(bw & 0xFFFF0000u);
            uint32_t pl01, pl23;
            CVT_BF16X2(pl01, v.y - hy, v.x - hx);
            CVT_BF16X2(pl23, v.w - hw, v.z - hz);
            const uint32_t addr = abase + (uint32_t)(r * 2048);
            *(uint2*)(sm + A_OFF + addr)         = make_uint2(ph01, ph23);
            *(uint2*)(sm + A_OFF + 16384 + addr) = make_uint2(pl01, pl23);
        }
    }

    // ---- per-warp frag addressing ----
    const int m0 = (wid & 3) * 16;
    const int s = wid >> 2;                      // nslice (48 cols)
    const int am = m0 + (lane & 15);
    const uint32_t a_row = smb + A_OFF + am * 256;
    const int a_kpar = lane >> 4;
    const int a_sw = lane & 7;
    const uint32_t b_row = (uint32_t)((s * 48 + ((lane >> 4) << 3) + (lane & 7)) * 48
                                      + (((lane >> 3) & 1) << 4));

    float acc[24];
#pragma unroll
    for (int i = 0; i < 24; i++) acc[i] = 0.f;

    const unsigned char* bsrc = g_WeB + (size_t)(g * 8) * 6144;
    int nb = 1;                                   // next buffer index (cycles 0,1,2)
    for (int kc = 0; kc < 8; kc++) {
        if (kc < 7) {
            const unsigned char* src = bsrc + (size_t)(kc + 1) * 6144;
            const uint32_t dst = smb + B_OFF + (uint32_t)nb * 9216;
            CP_ASYNC16(dst + dsto0, src + srco0);
            if (two) CP_ASYNC16(dst + dsto1, src + srco1);
            CP_COMMIT();
            CP_WAIT1();
            nb = (nb == 2) ? 0 : nb + 1;
        } else {
            CP_WAIT0();
        }
        __syncthreads();

        uint32_t ah[4], al[4];
        {
            uint32_t aaddr = a_row + (((kc * 2 + a_kpar) ^ a_sw) << 4);
            LDSM4(ah, aaddr);
            LDSM4(al, aaddr + 16384);
        }
        const uint32_t bb = smb + B_OFF + (uint32_t)((kc % 3) * 9216) + b_row;
#pragma unroll
        for (int p = 0; p < 3; p++) {
            uint32_t bh[4], bl[4];
            uint32_t baddr = bb + p * 768;        // 16 rows * 48B
            LDSM4(bh, baddr);
            LDSM4(bl, baddr + 4608);
            float* cA = acc + p * 8;
            float* cB = acc + p * 8 + 4;
            MMA(cA, ah, bh[0], bh[1]);
            MMA(cA, al, bh[0], bh[1]);
            MMA(cA, ah, bl[0], bl[1]);
            MMA(cB, ah, bh[2], bh[3]);
            MMA(cB, al, bh[2], bh[3]);
            MMA(cB, ah, bl[2], bl[3]);
        }
    }

    // ---------------- direct epilogue from fragments (R12) ----------------
    const float s3 = 0.5773502691896258f;    // 1/sqrt(3)
    const float sH = 0.08838834764831845f;   // 1/sqrt(128)
    const int lc0 = s * 16 + (lane & 3) * 2;
    const int rowa = m0 + (lane >> 2);

#pragma unroll
    for (int half = 0; half < 2; half++) {
        const int e = rowa + half * 8;
        const int j = js[e], i = is_[e];
        const float ev0 = evs[e * 3 + 0], ev1 = evs[e * 3 + 1], ev2 = evs[e * 3 + 2];
        const float* xh = g_xh + (size_t)j * 384;
        const float* vp = vec + (size_t)j * 384;
        float* dxp = d_x + (size_t)i * 128;
        float* dvp = d_vec + (size_t)i * 384;

#pragma unroll
        for (int sub = 0; sub < 2; sub++) {
            const int c = g * 32 + lc0 + sub * 8;      // output col in 0..127
            const int ai = sub * 4 + half * 2;
            float r1x = acc[ai],      r1y = acc[ai + 1];
            float r2x = acc[8 + ai],  r2y = acc[8 + ai + 1];
            float r3x = acc[16 + ai], r3y = acc[16 + ai + 1];

            float2 b0  = *(const float2*)(bes + c);
            float2 b1v = *(const float2*)(bes + 128 + c);
            float2 b2v = *(const float2*)(bes + 256 + c);
            float2 x1  = *(const float2*)(xh + c);
            float2 x2  = *(const float2*)(xh + 128 + c);
            float2 x3  = *(const float2*)(xh + 256 + c);

            float m1x = (r1x + b0.x) * x1.x * s3;
            float m1y = (r1y + b0.y) * x1.y * s3;
            float m2x = (r2x + b1v.x) * x2.x * s3;
            float m2y = (r2y + b1v.y) * x2.y * s3;
            float oxx = (r3x + b2v.x) * x3.x * s3;
            float oxy = (r3y + b2v.y) * x3.y * s3;
            RED2(dxp + c, oxx, oxy);

#pragma unroll
            for (int d = 0; d < 3; d++) {
                const float evd = (d == 0) ? ev0 : (d == 1) ? ev1 : ev2;
                float2 vj = *(const float2*)(vp + d * 128 + c);
                float ox = (m1x * vj.x + m2x * evd) * sH;
                float oy = (m1y * vj.y + m2y * evd) * sH;
                RED2(dvp + d * 128 + c, ox, oy);
            }
        }
    }
}

// ---------------- launch ----------------
extern "C" void kernel_launch(void* const* d_in, const int* in_sizes, int n_in,
                              void* d_out, int out_size)
{
    const float *x = nullptr, *vec = nullptr, *erbf = nullptr, *evec = nullptr;
    const float *W1 = nullptr, *b1 = nullptr, *W2 = nullptr, *b2 = nullptr;
    const float *We = nullptr, *be = nullptr;
    const int* eidx = nullptr;

    int seen384 = 0;
    for (int idx = 0; idx < n_in; idx++) {
        int s = in_sizes[idx];
        const void* p = d_in[idx];
        switch (s) {
            case 6400000:   x    = (const float*)p; break;
            case 19200000:  vec  = (const float*)p; break;
            case 102400000: erbf = (const float*)p; break;
            case 2400000:   evec = (const float*)p; break;
            case 1600000:   eidx = (const int*)p; break;
            case 8192:      W1   = (const float*)p; break;
            case 64:        b1   = (const float*)p; break;
            case 24576:     W2   = (const float*)p; break;
            case 49152:     We   = (const float*)p; break;
            case 384:
                if (seen384 == 0) b2 = (const float*)p; else be = (const float*)p;
                seen384++;
                break;
            default: break;
        }
    }

    float* out   = (float*)d_out;
    float* d_x   = out;
    float* d_vec = out + (size_t)NN * HH;

    cudaFuncSetAttribute(edge_kernel, cudaFuncAttributeMaxDynamicSharedMemorySize, EDGE_SMEM);

    long long n4 = out_size / 4;
    zero_kernel<<<(unsigned)((n4 + 255) / 256), 256>>>((float4*)out, n4);
    prep_we<<<192, 256>>>(We);
    node_kernel<<<NN / 16, 128>>>(x, W1, b1, W2, b2);
    edge_kernel<<<NTILES * 4, 256, EDGE_SMEM>>>(erbf, evec, eidx, be, vec, d_x, d_vec);
}

// round 17
// speedup vs baseline: 1.5027x; 1.5027x over previous
#include <cuda_runtime.h>
#include <cuda_bf16.h>
#include <cstdint>

#define NN 50000
#define EE 800000
#define HH 128
#define TH 384
#define NTILES (EE / 64)

// scratch: x_h [N][384] fp32; We in per-lane MMA-fragment layout:
//   index(g,kc,s,p,lane) = (((g*8+kc)*2+s)*3+p)*32 + lane ; 32B each = {hi 16B, lo 16B}
__device__ __align__(16) float g_xh[(size_t)NN * TH];
__device__ __align__(16) unsigned char g_WeB[4 * 8 * 2 * 3 * 32 * 32];   // 196608 B

// ---------------- PTX helpers ----------------
#define PACK2(d, lo, hi) \
    asm volatile("mov.b64 %0, {%1, %2};" : "=l"(d) : "f"(lo), "f"(hi))
#define UNPACK2(lo, hi, s) \
    asm volatile("mov.b64 {%0, %1}, %2;" : "=f"(lo), "=f"(hi) : "l"(s))
#define FMA2(c_, a_, b_) \
    asm volatile("fma.rn.f32x2 %0, %1, %2, %0;" : "+l"(c_) : "l"(a_), "l"(b_))
#define RED2(p_, a_, b_) \
    asm volatile("red.global.add.v2.f32 [%0], {%1, %2};" \
                 :: "l"(p_), "f"(a_), "f"(b_) : "memory")
#define CVT_BF16X2(d_, hi_, lo_) \
    asm volatile("cvt.rn.bf16x2.f32 %0, %1, %2;" : "=r"(d_) : "f"(hi_), "f"(lo_))

#define LDSM4(f_, addr_) \
    asm volatile("ldmatrix.sync.aligned.m8n8.x4.shared.b16 {%0,%1,%2,%3}, [%4];" \
        : "=r"((f_)[0]), "=r"((f_)[1]), "=r"((f_)[2]), "=r"((f_)[3]) : "r"(addr_))
#define MMA(c_, a_, b0_, b1_) \
    asm volatile("mma.sync.aligned.m16n8k16.row.col.f32.bf16.bf16.f32 " \
        "{%0,%1,%2,%3}, {%4,%5,%6,%7}, {%8,%9}, {%0,%1,%2,%3};" \
        : "+f"((c_)[0]), "+f"((c_)[1]), "+f"((c_)[2]), "+f"((c_)[3]) \
        : "r"((a_)[0]), "r"((a_)[1]), "r"((a_)[2]), "r"((a_)[3]), "r"(b0_), "r"(b1_))

// ---------------- zero output ----------------
__global__ void zero_kernel(float4* __restrict__ p, long long n4) {
    long long i = (long long)blockIdx.x * blockDim.x + threadIdx.x;
    if (i < n4) p[i] = make_float4(0.f, 0.f, 0.f, 0.f);
}

// ---------------- prep: We [K=128][N=384] fp32 -> bf16 hi/lo MMA-fragment layout -----
__global__ void prep_we(const float* __restrict__ We) {
    int idx = blockIdx.x * 256 + threadIdx.x;    // n*128 + k
    if (idx >= 384 * 128) return;
    int n = idx >> 7, k = idx & 127;
    float v = We[(size_t)k * 384 + n];
    __nv_bfloat16 h = __float2bfloat16(v);
    __nv_bfloat16 l = __float2bfloat16(v - __bfloat162float(h));
    // decompose n -> (p, g, s, u);  k -> (kc, kk)
    int p = n >> 7, r = n & 127;
    int g = r >> 5, w = r & 31;
    int s = w >> 4, u = w & 15;
    int kc = k >> 4, kk = k & 15;
    // PTX m16n8k16 B-operand mapping within the (u, kk) 16x16 sub-tile
    int lane = (u & 7) * 4 + ((kk & 7) >> 1);
    int reg  = ((u >> 3) << 1) + (kk >> 3);
    uint32_t off = (uint32_t)(((((g * 8 + kc) * 2 + s) * 3 + p) * 32 + lane) * 32
                              + reg * 4 + (kk & 1) * 2);
    *(unsigned short*)(g_WeB + off)      = __bfloat16_as_ushort(h);
    *(unsigned short*)(g_WeB + off + 16) = __bfloat16_as_ushort(l);
}

// ---------------- node kernel v2 (unchanged from R12) ----------------
__global__ __launch_bounds__(128) void node_kernel(
    const float* __restrict__ x, const float* __restrict__ W1,
    const float* __restrict__ b1, const float* __restrict__ W2,
    const float* __restrict__ b2)
{
    __shared__ __align__(16) float xs[128 * 16];
    __shared__ __align__(16) float w1s[128 * 64];
    __shared__ __align__(16) float hs[64 * 20];

    const int t = threadIdx.x;
    const int node0 = blockIdx.x * 16;

    {
        const float4* W14 = (const float4*)W1;
        float4* w1s4 = (float4*)w1s;
#pragma unroll
        for (int r = 0; r < 16; r++) w1s4[t + r * 128] = W14[t + r * 128];
    }
    const float4* x4 = (const float4*)x;
#pragma unroll
    for (int r = 0; r < 4; r++) {
        int idx = t + r * 128;
        int n = idx & 15, kq = idx >> 4;
        float4 v = x4[(size_t)(node0 + n) * 32 + kq];
        xs[(kq * 4 + 0) * 16 + n] = v.x;
        xs[(kq * 4 + 1) * 16 + n] = v.y;
        xs[(kq * 4 + 2) * 16 + n] = v.z;
        xs[(kq * 4 + 3) * 16 + n] = v.w;
    }
    __syncthreads();

    {
        const int c = t & 63, nh = t >> 6;
        unsigned long long a2[4];
        float b1c = b1[c];
        unsigned long long binit; PACK2(binit, b1c, b1c);
#pragma unroll
        for (int p = 0; p < 4; p++) a2[p] = binit;
        const unsigned long long* xp = (const unsigned long long*)xs;
#pragma unroll 4
        for (int k = 0; k < 128; k++) {
            float w = w1s[k * 64 + c];
            unsigned long long wp; PACK2(wp, w, w);
            const unsigned long long* xr = xp + k * 8 + nh * 4;
            FMA2(a2[0], xr[0], wp);
            FMA2(a2[1], xr[1], wp);
            FMA2(a2[2], xr[2], wp);
            FMA2(a2[3], xr[3], wp);
        }
#pragma unroll
        for (int p = 0; p < 4; p++) {
            float lo, hi; UNPACK2(lo, hi, a2[p]);
            lo = lo / (1.f + __expf(-lo)) * 1.6666666666666667f;
            hi = hi / (1.f + __expf(-hi)) * 1.6666666666666667f;
            unsigned long long pk; PACK2(pk, lo, hi);
            *(unsigned long long*)&hs[c * 20 + (nh * 4 + p) * 2] = pk;
        }
    }
    __syncthreads();

    {
        unsigned long long acc2[24];
#pragma unroll
        for (int a = 0; a < 24; a++) acc2[a] = 0ull;
#pragma unroll 2
        for (int k = 0; k < 64; k++) {
            const float* wr = W2 + k * 384 + t;
            float w0 = wr[0], w1 = wr[128], w2 = wr[256];
            unsigned long long wp0, wp1, wp2;
            PACK2(wp0, w0, w0); PACK2(wp1, w1, w1); PACK2(wp2, w2, w2);
            const unsigned long long* hp = (const unsigned long long*)&hs[k * 20];
#pragma unroll
            for (int p = 0; p < 8; p++) {
                unsigned long long hv = hp[p];
                FMA2(acc2[p],      hv, wp0);
                FMA2(acc2[8 + p],  hv, wp1);
                FMA2(acc2[16 + p], hv, wp2);
            }
        }
        const float bc0 = b2[t], bc1 = b2[t + 128], bc2 = b2[t + 256];
#pragma unroll
        for (int p = 0; p < 8; p++) {
            float* o0 = g_xh + (size_t)(node0 + 2 * p) * 384 + t;
            float* o1 = o0 + 384;
            float lo, hi;
            UNPACK2(lo, hi, acc2[p]);      o0[0]   = lo + bc0; o1[0]   = hi + bc0;
            UNPACK2(lo, hi, acc2[8 + p]);  o0[128] = lo + bc1; o1[128] = hi + bc1;
            UNPACK2(lo, hi, acc2[16 + p]); o0[256] = lo + bc2; o1[256] = hi + bc2;
        }
    }
}

// ---------------- edge kernel: smem A + direct-LDG B fragments, barrier-free loop ----
// 256 threads, M=64 edges x N=96 GEMM cols (col-group g: output cols {g*32..}+0/128/256).
// grid = 12500 edge-tiles * 4 col groups, col group fastest (L2 reuse of rbf tile).
// ONE __syncthreads total (after A build). B read directly from the global fragment
// layout via coalesced LDG.128 (L1/L2-resident: every block of the same g reads the
// same 48KB). smem = 36864 B.
//   [0:256) js  [256:512) is  [512:1280) evs[192]  [1280:2816) bes[384]
//   [4096:20480)  A hi 64x128 bf16 swizzled   [20480:36864) A lo
#define A_OFF 4096
#define EDGE_SMEM 36864

__global__ __launch_bounds__(256, 3) void edge_kernel(
    const float* __restrict__ edge_rbf, const float* __restrict__ edge_vector,
    const int* __restrict__ edge_index, const float* __restrict__ be,
    const float* __restrict__ vec, float* __restrict__ d_x, float* __restrict__ d_vec)
{
    extern __shared__ __align__(16) unsigned char sm[];
    const uint32_t smb = (uint32_t)__cvta_generic_to_shared(sm);
    const int tid = threadIdx.x;
    const int wid = tid >> 5;
    const int lane = tid & 31;
    const int g = blockIdx.x & 3;
    const int e0 = (blockIdx.x >> 2) * 64;

    int* js   = (int*)(sm);
    int* is_  = (int*)(sm + 256);
    float* evs = (float*)(sm + 512);
    float* bes = (float*)(sm + 1280);

    if (tid < 64) {
        js[tid]  = edge_index[e0 + tid];
        is_[tid] = edge_index[EE + e0 + tid];
    }
    if (tid < 192) evs[tid] = edge_vector[(size_t)e0 * 3 + tid];
    for (int id = tid; id < 384; id += 256) bes[id] = be[id];

    // ---- A: load fp32 rbf, truncation-split to bf16 hi/lo, swizzled store (R12) ----
    const float4* rbf4 = (const float4*)edge_rbf;
#pragma unroll
    for (int r = 0; r < 8; r++) {
        int fid = tid + r * 256;            // 0..2047
        int e = fid >> 5, q = fid & 31;     // edge row, float4 index (k0 = q*4)
        float4 v = rbf4[(size_t)(e0 + e) * 32 + q];
        uint32_t bx = __float_as_uint(v.x), by = __float_as_uint(v.y);
        uint32_t bz = __float_as_uint(v.z), bw = __float_as_uint(v.w);
        uint32_t ph01 = __byte_perm(bx, by, 0x7632);
        uint32_t ph23 = __byte_perm(bz, bw, 0x7632);
        float hx = __uint_as_float(bx & 0xFFFF0000u);
        float hy = __uint_as_float(by & 0xFFFF0000u);
        float hz = __uint_as_float(bz & 0xFFFF0000u);
        float hw = __uint_as_float(bw & 0xFFFF0000u);
        uint32_t pl01, pl23;
        CVT_BF16X2(pl01, v.y - hy, v.x - hx);
        CVT_BF16X2(pl23, v.w - hw, v.z - hz);
        uint32_t addr = (uint32_t)(e * 256 + (((q >> 1) ^ (e & 7)) << 4) + (q & 1) * 8);
        *(uint2*)(sm + A_OFF + addr)         = make_uint2(ph01, ph23);
        *(uint2*)(sm + A_OFF + 16384 + addr) = make_uint2(pl01, pl23);
    }

    // ---- per-warp frag addressing ----
    const int m0 = (wid & 3) * 16;
    const int s = wid >> 2;                      // nslice (48 cols)
    const int am = m0 + (lane & 15);
    const uint32_t a_row = smb + A_OFF + am * 256;
    const int a_kpar = lane >> 4;
    const int a_sw = lane & 7;
    // B fragment base for this (g, s, lane): per-kc stride 6144B, per-p stride 1024B
    const unsigned char* bptr = g_WeB + (size_t)g * 49152 + (size_t)s * 3072
                                + (size_t)lane * 32;

    float acc[24];
#pragma unroll
    for (int i = 0; i < 24; i++) acc[i] = 0.f;

    // single synchronization point of the whole kernel
    __syncthreads();

    // ---- barrier-free mainloop: LDSM(A) + LDG(B frags) + MMA, fully unrolled ----
#pragma unroll
    for (int kc = 0; kc < 8; kc++) {
        uint32_t ah[4], al[4];
        {
            uint32_t aaddr = a_row + (((kc * 2 + a_kpar) ^ a_sw) << 4);
            LDSM4(ah, aaddr);
            LDSM4(al, aaddr + 16384);
        }
        const unsigned char* bk = bptr + kc * 6144;
#pragma unroll
        for (int p = 0; p < 3; p++) {
            uint4 h4 = *(const uint4*)(bk + p * 1024);
            uint4 l4 = *(const uint4*)(bk + p * 1024 + 16);
            float* cA = acc + p * 8;
            float* cB = acc + p * 8 + 4;
            MMA(cA, ah, h4.x, h4.y);
            MMA(cA, al, h4.x, h4.y);
            MMA(cA, ah, l4.x, l4.y);
            MMA(cB, ah, h4.z, h4.w);
            MMA(cB, al, h4.z, h4.w);
            MMA(cB, ah, l4.z, l4.w);
        }
    }

    // ---------------- direct epilogue from fragments (R12) ----------------
    const float s3 = 0.5773502691896258f;    // 1/sqrt(3)
    const float sH = 0.08838834764831845f;   // 1/sqrt(128)
    const int lc0 = s * 16 + (lane & 3) * 2;
    const int rowa = m0 + (lane >> 2);

#pragma unroll
    for (int half = 0; half < 2; half++) {
        const int e = rowa + half * 8;
        const int j = js[e], i = is_[e];
        const float ev0 = evs[e * 3 + 0], ev1 = evs[e * 3 + 1], ev2 = evs[e * 3 + 2];
        const float* xh = g_xh + (size_t)j * 384;
        const float* vp = vec + (size_t)j * 384;
        float* dxp = d_x + (size_t)i * 128;
        float* dvp = d_vec + (size_t)i * 384;

#pragma unroll
        for (int sub = 0; sub < 2; sub++) {
            const int c = g * 32 + lc0 + sub * 8;      // output col in 0..127
            const int ai = sub * 4 + half * 2;
            float r1x = acc[ai],      r1y = acc[ai + 1];
            float r2x = acc[8 + ai],  r2y = acc[8 + ai + 1];
            float r3x = acc[16 + ai], r3y = acc[16 + ai + 1];

            float2 b0  = *(const float2*)(bes + c);
            float2 b1v = *(const float2*)(bes + 128 + c);
            float2 b2v = *(const float2*)(bes + 256 + c);
            float2 x1  = *(const float2*)(xh + c);
            float2 x2  = *(const float2*)(xh + 128 + c);
            float2 x3  = *(const float2*)(xh + 256 + c);

            float m1x = (r1x + b0.x) * x1.x * s3;
            float m1y = (r1y + b0.y) * x1.y * s3;
            float m2x = (r2x + b1v.x) * x2.x * s3;
            float m2y = (r2y + b1v.y) * x2.y * s3;
            float oxx = (r3x + b2v.x) * x3.x * s3;
            float oxy = (r3y + b2v.y) * x3.y * s3;
            RED2(dxp + c, oxx, oxy);

#pragma unroll
            for (int d = 0; d < 3; d++) {
                const float evd = (d == 0) ? ev0 : (d == 1) ? ev1 : ev2;
                float2 vj = *(const float2*)(vp + d * 128 + c);
                float ox = (m1x * vj.x + m2x * evd) * sH;
                float oy = (m1y * vj.y + m2y * evd) * sH;
                RED2(dvp + d * 128 + c, ox, oy);
            }
        }
    }
}

// ---------------- launch ----------------
extern "C" void kernel_launch(void* const* d_in, const int* in_sizes, int n_in,
                              void* d_out, int out_size)
{
    const float *x = nullptr, *vec = nullptr, *erbf = nullptr, *evec = nullptr;
    const float *W1 = nullptr, *b1 = nullptr, *W2 = nullptr, *b2 = nullptr;
    const float *We = nullptr, *be = nullptr;
    const int* eidx = nullptr;

    int seen384 = 0;
    for (int idx = 0; idx < n_in; idx++) {
        int s = in_sizes[idx];
        const void* p = d_in[idx];
        switch (s) {
            case 6400000:   x    = (const float*)p; break;
            case 19200000:  vec  = (const float*)p; break;
            case 102400000: erbf = (const float*)p; break;
            case 2400000:   evec = (const float*)p; break;
            case 1600000:   eidx = (const int*)p; break;
            case 8192:      W1   = (const float*)p; break;
            case 64:        b1   = (const float*)p; break;
            case 24576:     W2   = (const float*)p; break;
            case 49152:     We   = (const float*)p; break;
            case 384:
                if (seen384 == 0) b2 = (const float*)p; else be = (const float*)p;
                seen384++;
                break;
            default: break;
        }
    }

    float* out   = (float*)d_out;
    float* d_x   = out;
    float* d_vec = out + (size_t)NN * HH;

    cudaFuncSetAttribute(edge_kernel, cudaFuncAttributeMaxDynamicSharedMemorySize, EDGE_SMEM);

    long long n4 = out_size / 4;
    zero_kernel<<<(unsigned)((n4 + 255) / 256), 256>>>((float4*)out, n4);
    prep_we<<<192, 256>>>(We);
    node_kernel<<<NN / 16, 128>>>(x, W1, b1, W2, b2);
    edge_kernel<<<NTILES * 4, 256, EDGE_SMEM>>>(erbf, evec, eidx, be, vec, d_x, d_vec);
}